// round 14
// baseline (speedup 1.0000x reference)
#include <cuda_runtime.h>

// CapsNet dynamic routing, FFMA2 GEMMs.
// R14: occupancy/tail fixes. gemm_S split-K 146 (2 CTA/SM, 16 warps);
// gemm_Ya split-K 4 (tail = half-size CTAs); init/compute_C folded (10 launches).
// x: [256, 2401, 8] fp32   W: [2401, 8, 16, 8] fp32   out: [256, 8, 16] fp32

#define IN_CAPS 2401
#define BATCH 256
#define KTOT 19208                 // 2401*8
#define NOC 128                    // 8*16
#define NSPLIT 146                 // gemm_S split-K: 65 splits x17 slabs + 81 x16
#define YSPLIT 4

typedef unsigned long long ull;

__device__ float g_Spart[(size_t)NSPLIT * BATCH * NOC];  // 19.1 MB
__device__ float g_V[BATCH * NOC];
__device__ float g_b[IN_CAPS * 8];
__device__ float g_bp[YSPLIT][IN_CAPS * 8];
__device__ float g_C[IN_CAPS * 8];

__device__ __forceinline__ void ffma2(ull& acc, ull a, ull b) {
    asm("fma.rn.f32x2 %0, %1, %2, %0;" : "+l"(acc) : "l"(a), "l"(b));
}
__device__ __forceinline__ ull pack2(float x) {
    ull r;
    unsigned u = __float_as_uint(x);
    asm("mov.b64 %0, {%1, %1};" : "=l"(r) : "r"(u));
    return r;
}

// ---------------------------------------------------------------------------
// b = (first ? 0 : b) + sum of 4 Ya partials; softmax over o -> C.
__global__ void __launch_bounds__(128) compute_C_kernel(int first) {
    int i = blockIdx.x * 128 + threadIdx.x;
    if (i >= IN_CAPS) return;
    float bv[8];
#pragma unroll
    for (int o = 0; o < 8; o++) {
        float b = first ? 0.0f : g_b[i * 8 + o];
#pragma unroll
        for (int s = 0; s < YSPLIT; s++) b += g_bp[s][i * 8 + o];
        bv[o] = b;
        g_b[i * 8 + o] = b;
    }
    float mx = -1e30f;
#pragma unroll
    for (int o = 0; o < 8; o++) mx = fmaxf(mx, bv[o]);
    float sum = 0.0f;
#pragma unroll
    for (int o = 0; o < 8; o++) { bv[o] = expf(bv[o] - mx); sum += bv[o]; }
    float inv = 1.0f / sum;
#pragma unroll
    for (int o = 0; o < 8; o++) g_C[i * 8 + o] = bv[o] * inv;
}

// ---------------------------------------------------------------------------
// S = X @ (C .* W), split-K partials. grid (2, 146) x 256 thr -> 292 CTAs,
// 2 CTA/SM (16 warps). uniformC=1 on iter 0 (softmax of zeros = 0.125).
__global__ void __launch_bounds__(256, 2) gemm_S_kernel(const float* __restrict__ X,
                                                        const float* __restrict__ W,
                                                        int uniformC) {
    __shared__ __align__(16) float Xs[8][132];
    __shared__ __align__(16) float Ms[8][132];

    int b0 = blockIdx.x * 128;
    int split = blockIdx.y;
    int sbase = split * 16 + min(split, 65);       // slab = capsule index
    int scnt = 16 + (split < 65 ? 1 : 0);
    int kstart = sbase * 8;
    int kend = (sbase + scnt) * 8;
    int t = threadIdx.x;
    int tx = t & 15, ty = t >> 4;

    ull acc[8][4];
#pragma unroll
    for (int r = 0; r < 8; r++)
#pragma unroll
        for (int j = 0; j < 4; j++) acc[r][j] = 0ull;

    int xbb = t >> 1, xkp = (t & 1) * 4;
    int wl = t * 4;
    int wo = wl >> 7, wc = (wl >> 3) & 15, wd = wl & 7;
    int wcol = wo * 16 + wc;

    float4 xv = *reinterpret_cast<const float4*>(X + (size_t)(b0 + xbb) * KTOT + kstart + xkp);
    float4 wv = *reinterpret_cast<const float4*>(W + (size_t)(kstart >> 3) * 1024 + wl);
    float cc = uniformC ? 0.125f : g_C[(kstart >> 3) * 8 + wo];

    for (int k0 = kstart; k0 < kend; k0 += 8) {
        __syncthreads();
        Xs[xkp + 0][xbb] = xv.x; Xs[xkp + 1][xbb] = xv.y;
        Xs[xkp + 2][xbb] = xv.z; Xs[xkp + 3][xbb] = xv.w;
        Ms[wd + 0][wcol] = cc * wv.x; Ms[wd + 1][wcol] = cc * wv.y;
        Ms[wd + 2][wcol] = cc * wv.z; Ms[wd + 3][wcol] = cc * wv.w;
        __syncthreads();

        int kn = k0 + 8;
        if (kn < kend) {
            xv = *reinterpret_cast<const float4*>(X + (size_t)(b0 + xbb) * KTOT + kn + xkp);
            wv = *reinterpret_cast<const float4*>(W + (size_t)(kn >> 3) * 1024 + wl);
            cc = uniformC ? 0.125f : g_C[(kn >> 3) * 8 + wo];
        }

#pragma unroll
        for (int kk = 0; kk < 8; kk++) {
            ull mv[4];
#pragma unroll
            for (int jj = 0; jj < 4; jj++)
                mv[jj] = *reinterpret_cast<const ull*>(&Ms[kk][jj * 32 + tx * 2]);
            float4 xa = *reinterpret_cast<const float4*>(&Xs[kk][ty * 8]);
            float4 xb = *reinterpret_cast<const float4*>(&Xs[kk][ty * 8 + 4]);
            float xr[8] = {xa.x, xa.y, xa.z, xa.w, xb.x, xb.y, xb.z, xb.w};
#pragma unroll
            for (int rr = 0; rr < 8; rr++) {
                ull a = pack2(xr[rr]);
#pragma unroll
                for (int jj = 0; jj < 4; jj++) ffma2(acc[rr][jj], a, mv[jj]);
            }
        }
    }

    float* out = g_Spart + (size_t)split * (BATCH * NOC);
#pragma unroll
    for (int rr = 0; rr < 8; rr++) {
        int bb = b0 + ty * 8 + rr;
#pragma unroll
        for (int jj = 0; jj < 4; jj++)
            *reinterpret_cast<float2*>(out + (size_t)bb * NOC + jj * 32 + tx * 2) =
                *reinterpret_cast<float2*>(&acc[rr][jj]);
    }
}

// ---------------------------------------------------------------------------
// Sum 146 partials + squash. Coalesced: gg = id>>2 (contiguous columns across
// lanes), q = id&3 (partial lane). grid 128 x 256 thr.
__global__ void __launch_bounds__(256) reduce_squash_kernel(float* __restrict__ out, int last) {
    int id = blockIdx.x * 256 + threadIdx.x;
    int gg = id >> 2;
    int q = id & 3;
    const float4* sp = reinterpret_cast<const float4*>(g_Spart);

    float4 s = make_float4(0.f, 0.f, 0.f, 0.f);
#pragma unroll 8
    for (int p = q; p < NSPLIT; p += 4) {
        float4 v = sp[(size_t)p * (BATCH * NOC / 4) + gg];
        s.x += v.x; s.y += v.y; s.z += v.z; s.w += v.w;
    }
#pragma unroll
    for (int off = 1; off <= 2; off <<= 1) {
        s.x += __shfl_xor_sync(0xffffffffu, s.x, off);
        s.y += __shfl_xor_sync(0xffffffffu, s.y, off);
        s.z += __shfl_xor_sync(0xffffffffu, s.z, off);
        s.w += __shfl_xor_sync(0xffffffffu, s.w, off);
    }
    float msq = s.x * s.x + s.y * s.y + s.z * s.z + s.w * s.w;
    msq += __shfl_xor_sync(0xffffffffu, msq, 4);
    msq += __shfl_xor_sync(0xffffffffu, msq, 8);
    float f = sqrtf(msq) / (1.0f + msq);
    float4 v = make_float4(s.x * f, s.y * f, s.z * f, s.w * f);
    if (q == 0) {
        reinterpret_cast<float4*>(g_V)[gg] = v;
        if (last) reinterpret_cast<float4*>(out)[gg] = v;
    }
}

// ---------------------------------------------------------------------------
// Y = X^T @ V, K-split 4 over batch (K=64/CTA), fused agreement -> g_bp[split].
// grid (301, 4) x 128 thr, occ 4. CTA tile 64 K-rows x 128 cols, per-thread 8x8.
__global__ void __launch_bounds__(128, 4) gemm_Ya_kernel(const float* __restrict__ X,
                                                         const float* __restrict__ W) {
    __shared__ float Xts[8][68];
    __shared__ float Vs[8][132];

    int r0 = blockIdx.x * 64;
    int split = blockIdx.y;
    int kbeg = split * 64, kfin = kbeg + 64;
    int t = threadIdx.x;
    int tx = t & 15, ty = t >> 4;

    ull acc[8][4];
#pragma unroll
    for (int r = 0; r < 8; r++)
#pragma unroll
        for (int j = 0; j < 4; j++) acc[r][j] = 0ull;

    int lkk = t >> 4;            // 0..7
    int lq = (t & 15) * 4;       // 0..60
    bool xok = (r0 + lq) < KTOT;

    float4 xv = xok ? *reinterpret_cast<const float4*>(X + (size_t)(kbeg + lkk) * KTOT + r0 + lq)
                    : make_float4(0.f, 0.f, 0.f, 0.f);
    float4 va = *reinterpret_cast<const float4*>(g_V + (kbeg + lkk) * NOC + lq);
    float4 vb = *reinterpret_cast<const float4*>(g_V + (kbeg + lkk) * NOC + lq + 64);

    for (int k0 = kbeg; k0 < kfin; k0 += 8) {
        __syncthreads();
        *reinterpret_cast<float4*>(&Xts[lkk][lq]) = xv;
        *reinterpret_cast<float4*>(&Vs[lkk][lq]) = va;
        *reinterpret_cast<float4*>(&Vs[lkk][lq + 64]) = vb;
        __syncthreads();

        int kn = k0 + 8;
        if (kn < kfin) {
            xv = xok ? *reinterpret_cast<const float4*>(X + (size_t)(kn + lkk) * KTOT + r0 + lq)
                     : make_float4(0.f, 0.f, 0.f, 0.f);
            va = *reinterpret_cast<const float4*>(g_V + (kn + lkk) * NOC + lq);
            vb = *reinterpret_cast<const float4*>(g_V + (kn + lkk) * NOC + lq + 64);
        }

#pragma unroll
        for (int kk = 0; kk < 8; kk++) {
            ull mv[4];
#pragma unroll
            for (int jj = 0; jj < 4; jj++)
                mv[jj] = *reinterpret_cast<const ull*>(&Vs[kk][jj * 32 + tx * 2]);
            float4 xa = *reinterpret_cast<const float4*>(&Xts[kk][ty * 8]);
            float4 xb = *reinterpret_cast<const float4*>(&Xts[kk][ty * 8 + 4]);
            float xr[8] = {xa.x, xa.y, xa.z, xa.w, xb.x, xb.y, xb.z, xb.w};
#pragma unroll
            for (int rr = 0; rr < 8; rr++) {
                ull a = pack2(xr[rr]);
#pragma unroll
                for (int jj = 0; jj < 4; jj++) ffma2(acc[rr][jj], a, mv[jj]);
            }
        }
    }

    // Agreement partial: a[i,o] = (1/B) sum_{c,d,k in quarter} W * Y
    int i = r0 / 8 + ty;
    int iw = min(i, IN_CAPS - 1);
    int ohi = tx >> 3;
    int c = (tx & 7) * 2;
    float s[4];
#pragma unroll
    for (int jj = 0; jj < 4; jj++) {
        int oo = jj * 2 + ohi;
        const float4* wp = reinterpret_cast<const float4*>(W + (size_t)iw * 1024 + oo * 128 + c * 8);
        float4 w0 = wp[0], w1 = wp[1], w2 = wp[2], w3 = wp[3];
        float wlo[8] = {w0.x, w0.y, w0.z, w0.w, w1.x, w1.y, w1.z, w1.w};
        float whi[8] = {w2.x, w2.y, w2.z, w2.w, w3.x, w3.y, w3.z, w3.w};
        float sum = 0.0f;
#pragma unroll
        for (int d = 0; d < 8; d++) {
            float2 y = *reinterpret_cast<float2*>(&acc[d][jj]);
            sum += wlo[d] * y.x + whi[d] * y.y;
        }
        s[jj] = sum;
    }
#pragma unroll
    for (int jj = 0; jj < 4; jj++) {
        s[jj] += __shfl_xor_sync(0xffffffffu, s[jj], 1);
        s[jj] += __shfl_xor_sync(0xffffffffu, s[jj], 2);
        s[jj] += __shfl_xor_sync(0xffffffffu, s[jj], 4);
    }
    if ((tx & 7) == 0 && i < IN_CAPS) {
#pragma unroll
        for (int jj = 0; jj < 4; jj++)
            g_bp[split][i * 8 + jj * 2 + ohi] = s[jj] * (1.0f / 256.0f);
    }
}

// ---------------------------------------------------------------------------
extern "C" void kernel_launch(void* const* d_in, const int* in_sizes, int n_in,
                              void* d_out, int out_size) {
    const float* x;
    const float* W;
    if (in_sizes[0] == BATCH * KTOT) {
        x = (const float*)d_in[0];
        W = (const float*)d_in[1];
    } else {
        x = (const float*)d_in[1];
        W = (const float*)d_in[0];
    }
    float* out = (float*)d_out;

    for (int it = 0; it < 3; it++) {
        gemm_S_kernel<<<dim3(2, NSPLIT), 256>>>(x, W, it == 0 ? 1 : 0);
        reduce_squash_kernel<<<128, 256>>>(out, it == 2 ? 1 : 0);
        if (it < 2) {
            gemm_Ya_kernel<<<dim3(301, YSPLIT), 128>>>(x, W);
            compute_C_kernel<<<19, 128>>>(it == 0 ? 1 : 0);
        }
    }
}

// round 15
// speedup vs baseline: 1.0851x; 1.0851x over previous
#include <cuda_runtime.h>

// CapsNet dynamic routing, FFMA2 GEMMs.
// R15: exact R13 config (best: 147.6us) + launch elimination only:
// init_kernel removed (uniformC flag on iter-0 gemm_S, first flag on compute_C).
// x: [256, 2401, 8] fp32   W: [2401, 8, 16, 8] fp32   out: [256, 8, 16] fp32

#define IN_CAPS 2401
#define BATCH 256
#define KTOT 19208                 // 2401*8
#define NOC 128                    // 8*16
#define NSPLIT 73
#define CHUNK 264                  // 72*264 + 200 = 19208, multiples of 8

typedef unsigned long long ull;

__device__ float g_Spart[(size_t)NSPLIT * BATCH * NOC];  // 9.57 MB
__device__ float g_V[BATCH * NOC];
__device__ float g_b[IN_CAPS * 8];
__device__ float g_bp[2][IN_CAPS * 8];
__device__ float g_C[IN_CAPS * 8];

__device__ __forceinline__ void ffma2(ull& acc, ull a, ull b) {
    asm("fma.rn.f32x2 %0, %1, %2, %0;" : "+l"(acc) : "l"(a), "l"(b));
}
__device__ __forceinline__ ull pack2(float x) {
    ull r;
    unsigned u = __float_as_uint(x);
    asm("mov.b64 %0, {%1, %1};" : "=l"(r) : "r"(u));
    return r;
}

// ---------------------------------------------------------------------------
// b = (first ? 0 : b) + 2 Ya partials; softmax over o -> C.
__global__ void __launch_bounds__(128) compute_C_kernel(int first) {
    int i = blockIdx.x * 128 + threadIdx.x;
    if (i >= IN_CAPS) return;
    float bv[8];
#pragma unroll
    for (int o = 0; o < 8; o++) {
        float b = first ? 0.0f : g_b[i * 8 + o];
        b += g_bp[0][i * 8 + o] + g_bp[1][i * 8 + o];
        bv[o] = b;
        g_b[i * 8 + o] = b;
    }
    float mx = -1e30f;
#pragma unroll
    for (int o = 0; o < 8; o++) mx = fmaxf(mx, bv[o]);
    float sum = 0.0f;
#pragma unroll
    for (int o = 0; o < 8; o++) { bv[o] = expf(bv[o] - mx); sum += bv[o]; }
    float inv = 1.0f / sum;
#pragma unroll
    for (int o = 0; o < 8; o++) g_C[i * 8 + o] = bv[o] * inv;
}

// ---------------------------------------------------------------------------
// S = X @ (C .* W), split-K partials. grid (2, 73) x 256 thr.
// uniformC=1 on iter 0 (softmax of zeros = 0.125) — no init kernel needed.
__global__ void __launch_bounds__(256, 2) gemm_S_kernel(const float* __restrict__ X,
                                                        const float* __restrict__ W,
                                                        int uniformC) {
    __shared__ __align__(16) float Xs[8][132];
    __shared__ __align__(16) float Ms[8][132];

    int b0 = blockIdx.x * 128;
    int kstart = blockIdx.y * CHUNK;
    int kend = min(kstart + CHUNK, KTOT);
    int t = threadIdx.x;
    int tx = t & 15, ty = t >> 4;

    ull acc[8][4];
#pragma unroll
    for (int r = 0; r < 8; r++)
#pragma unroll
        for (int j = 0; j < 4; j++) acc[r][j] = 0ull;

    int xbb = t >> 1, xkp = (t & 1) * 4;
    int wl = t * 4;
    int wo = wl >> 7, wc = (wl >> 3) & 15, wd = wl & 7;
    int wcol = wo * 16 + wc;

    float4 xv = *reinterpret_cast<const float4*>(X + (size_t)(b0 + xbb) * KTOT + kstart + xkp);
    float4 wv = *reinterpret_cast<const float4*>(W + (size_t)(kstart >> 3) * 1024 + wl);
    float cc = uniformC ? 0.125f : g_C[(kstart >> 3) * 8 + wo];

    for (int k0 = kstart; k0 < kend; k0 += 8) {
        __syncthreads();
        Xs[xkp + 0][xbb] = xv.x; Xs[xkp + 1][xbb] = xv.y;
        Xs[xkp + 2][xbb] = xv.z; Xs[xkp + 3][xbb] = xv.w;
        Ms[wd + 0][wcol] = cc * wv.x; Ms[wd + 1][wcol] = cc * wv.y;
        Ms[wd + 2][wcol] = cc * wv.z; Ms[wd + 3][wcol] = cc * wv.w;
        __syncthreads();

        int kn = k0 + 8;
        if (kn < kend) {
            xv = *reinterpret_cast<const float4*>(X + (size_t)(b0 + xbb) * KTOT + kn + xkp);
            wv = *reinterpret_cast<const float4*>(W + (size_t)(kn >> 3) * 1024 + wl);
            cc = uniformC ? 0.125f : g_C[(kn >> 3) * 8 + wo];
        }

#pragma unroll
        for (int kk = 0; kk < 8; kk++) {
            ull mv[4];
#pragma unroll
            for (int jj = 0; jj < 4; jj++)
                mv[jj] = *reinterpret_cast<const ull*>(&Ms[kk][jj * 32 + tx * 2]);
            float4 xa = *reinterpret_cast<const float4*>(&Xs[kk][ty * 8]);
            float4 xb = *reinterpret_cast<const float4*>(&Xs[kk][ty * 8 + 4]);
            float xr[8] = {xa.x, xa.y, xa.z, xa.w, xb.x, xb.y, xb.z, xb.w};
#pragma unroll
            for (int rr = 0; rr < 8; rr++) {
                ull a = pack2(xr[rr]);
#pragma unroll
                for (int jj = 0; jj < 4; jj++) ffma2(acc[rr][jj], a, mv[jj]);
            }
        }
    }

    float* out = g_Spart + (size_t)blockIdx.y * (BATCH * NOC);
#pragma unroll
    for (int rr = 0; rr < 8; rr++) {
        int bb = b0 + ty * 8 + rr;
#pragma unroll
        for (int jj = 0; jj < 4; jj++)
            *reinterpret_cast<float2*>(out + (size_t)bb * NOC + jj * 32 + tx * 2) =
                *reinterpret_cast<float2*>(&acc[rr][jj]);
    }
}

// ---------------------------------------------------------------------------
// Sum 73 partials + squash. Coalesced: gg = id>>2 (contiguous columns across
// lanes), q = id&3 (partial lane). grid 128 x 256 thr.
__global__ void __launch_bounds__(256) reduce_squash_kernel(float* __restrict__ out, int last) {
    int id = blockIdx.x * 256 + threadIdx.x;
    int gg = id >> 2;
    int q = id & 3;
    const float4* sp = reinterpret_cast<const float4*>(g_Spart);

    float4 s = make_float4(0.f, 0.f, 0.f, 0.f);
#pragma unroll 8
    for (int p = q; p < NSPLIT; p += 4) {
        float4 v = sp[(size_t)p * (BATCH * NOC / 4) + gg];
        s.x += v.x; s.y += v.y; s.z += v.z; s.w += v.w;
    }
#pragma unroll
    for (int off = 1; off <= 2; off <<= 1) {
        s.x += __shfl_xor_sync(0xffffffffu, s.x, off);
        s.y += __shfl_xor_sync(0xffffffffu, s.y, off);
        s.z += __shfl_xor_sync(0xffffffffu, s.z, off);
        s.w += __shfl_xor_sync(0xffffffffu, s.w, off);
    }
    float msq = s.x * s.x + s.y * s.y + s.z * s.z + s.w * s.w;
    msq += __shfl_xor_sync(0xffffffffu, msq, 4);
    msq += __shfl_xor_sync(0xffffffffu, msq, 8);
    float f = sqrtf(msq) / (1.0f + msq);
    float4 v = make_float4(s.x * f, s.y * f, s.z * f, s.w * f);
    if (q == 0) {
        reinterpret_cast<float4*>(g_V)[gg] = v;
        if (last) reinterpret_cast<float4*>(out)[gg] = v;
    }
}

// ---------------------------------------------------------------------------
// Y = X^T @ V, K-split 2 over batch, fused agreement into g_bp[split].
// grid (301, 2) x 128 thr, occ 4 (best measured Ya config).
// CTA tile 64 K-rows x 128 cols; per-thread 8x8. ty owns capsule r0/8+ty.
__global__ void __launch_bounds__(128, 4) gemm_Ya_kernel(const float* __restrict__ X,
                                                         const float* __restrict__ W) {
    __shared__ float Xts[8][68];
    __shared__ float Vs[8][132];

    int r0 = blockIdx.x * 64;
    int split = blockIdx.y;
    int kbeg = split * 128, kfin = kbeg + 128;
    int t = threadIdx.x;
    int tx = t & 15, ty = t >> 4;

    ull acc[8][4];
#pragma unroll
    for (int r = 0; r < 8; r++)
#pragma unroll
        for (int j = 0; j < 4; j++) acc[r][j] = 0ull;

    int lkk = t >> 4;            // 0..7
    int lq = (t & 15) * 4;       // 0..60
    bool xok = (r0 + lq) < KTOT;

    float4 xv = xok ? *reinterpret_cast<const float4*>(X + (size_t)(kbeg + lkk) * KTOT + r0 + lq)
                    : make_float4(0.f, 0.f, 0.f, 0.f);
    float4 va = *reinterpret_cast<const float4*>(g_V + (kbeg + lkk) * NOC + lq);
    float4 vb = *reinterpret_cast<const float4*>(g_V + (kbeg + lkk) * NOC + lq + 64);

    for (int k0 = kbeg; k0 < kfin; k0 += 8) {
        __syncthreads();
        *reinterpret_cast<float4*>(&Xts[lkk][lq]) = xv;
        *reinterpret_cast<float4*>(&Vs[lkk][lq]) = va;
        *reinterpret_cast<float4*>(&Vs[lkk][lq + 64]) = vb;
        __syncthreads();

        int kn = k0 + 8;
        if (kn < kfin) {
            xv = xok ? *reinterpret_cast<const float4*>(X + (size_t)(kn + lkk) * KTOT + r0 + lq)
                     : make_float4(0.f, 0.f, 0.f, 0.f);
            va = *reinterpret_cast<const float4*>(g_V + (kn + lkk) * NOC + lq);
            vb = *reinterpret_cast<const float4*>(g_V + (kn + lkk) * NOC + lq + 64);
        }

#pragma unroll
        for (int kk = 0; kk < 8; kk++) {
            ull mv[4];
#pragma unroll
            for (int jj = 0; jj < 4; jj++)
                mv[jj] = *reinterpret_cast<const ull*>(&Vs[kk][jj * 32 + tx * 2]);
            float4 xa = *reinterpret_cast<const float4*>(&Xts[kk][ty * 8]);
            float4 xb = *reinterpret_cast<const float4*>(&Xts[kk][ty * 8 + 4]);
            float xr[8] = {xa.x, xa.y, xa.z, xa.w, xb.x, xb.y, xb.z, xb.w};
#pragma unroll
            for (int rr = 0; rr < 8; rr++) {
                ull a = pack2(xr[rr]);
#pragma unroll
                for (int jj = 0; jj < 4; jj++) ffma2(acc[rr][jj], a, mv[jj]);
            }
        }
    }

    // Agreement partial: a[i,o] = (1/B) sum_{c,d,k in half} W * Y
    int i = r0 / 8 + ty;
    int iw = min(i, IN_CAPS - 1);
    int ohi = tx >> 3;
    int c = (tx & 7) * 2;
    float s[4];
#pragma unroll
    for (int jj = 0; jj < 4; jj++) {
        int oo = jj * 2 + ohi;
        const float4* wp = reinterpret_cast<const float4*>(W + (size_t)iw * 1024 + oo * 128 + c * 8);
        float4 w0 = wp[0], w1 = wp[1], w2 = wp[2], w3 = wp[3];
        float wlo[8] = {w0.x, w0.y, w0.z, w0.w, w1.x, w1.y, w1.z, w1.w};
        float whi[8] = {w2.x, w2.y, w2.z, w2.w, w3.x, w3.y, w3.z, w3.w};
        float sum = 0.0f;
#pragma unroll
        for (int d = 0; d < 8; d++) {
            float2 y = *reinterpret_cast<float2*>(&acc[d][jj]);
            sum += wlo[d] * y.x + whi[d] * y.y;
        }
        s[jj] = sum;
    }
#pragma unroll
    for (int jj = 0; jj < 4; jj++) {
        s[jj] += __shfl_xor_sync(0xffffffffu, s[jj], 1);
        s[jj] += __shfl_xor_sync(0xffffffffu, s[jj], 2);
        s[jj] += __shfl_xor_sync(0xffffffffu, s[jj], 4);
    }
    if ((tx & 7) == 0 && i < IN_CAPS) {
#pragma unroll
        for (int jj = 0; jj < 4; jj++)
            g_bp[split][i * 8 + jj * 2 + ohi] = s[jj] * (1.0f / 256.0f);
    }
}

// ---------------------------------------------------------------------------
extern "C" void kernel_launch(void* const* d_in, const int* in_sizes, int n_in,
                              void* d_out, int out_size) {
    const float* x;
    const float* W;
    if (in_sizes[0] == BATCH * KTOT) {
        x = (const float*)d_in[0];
        W = (const float*)d_in[1];
    } else {
        x = (const float*)d_in[1];
        W = (const float*)d_in[0];
    }
    float* out = (float*)d_out;

    for (int it = 0; it < 3; it++) {
        gemm_S_kernel<<<dim3(2, NSPLIT), 256>>>(x, W, it == 0 ? 1 : 0);
        reduce_squash_kernel<<<128, 256>>>(out, it == 2 ? 1 : 0);
        if (it < 2) {
            gemm_Ya_kernel<<<dim3(301, 2), 128>>>(x, W);
            compute_C_kernel<<<19, 128>>>(it == 0 ? 1 : 0);
        }
    }
}

// round 16
// speedup vs baseline: 1.2561x; 1.1576x over previous
#include <cuda_runtime.h>

// CapsNet dynamic routing, FFMA2 GEMMs.
// R16: R13 config byte-faithful (best measured: 147.6us) with ONE change:
// compute_C vectorized (6x float4 MLP loads, __expf, float4 stores).
// x: [256, 2401, 8] fp32   W: [2401, 8, 16, 8] fp32   out: [256, 8, 16] fp32

#define IN_CAPS 2401
#define BATCH 256
#define KTOT 19208                 // 2401*8
#define NOC 128                    // 8*16
#define NSPLIT 73
#define CHUNK 264                  // 72*264 + 200 = 19208, multiples of 8

typedef unsigned long long ull;

__device__ float g_Spart[(size_t)NSPLIT * BATCH * NOC];  // 9.57 MB
__device__ float g_V[BATCH * NOC];
__device__ __align__(16) float g_b[IN_CAPS * 8];
__device__ __align__(16) float g_bp[2][IN_CAPS * 8];
__device__ __align__(16) float g_C[IN_CAPS * 8];

__device__ __forceinline__ void ffma2(ull& acc, ull a, ull b) {
    asm("fma.rn.f32x2 %0, %1, %2, %0;" : "+l"(acc) : "l"(a), "l"(b));
}
__device__ __forceinline__ ull pack2(float x) {
    ull r;
    unsigned u = __float_as_uint(x);
    asm("mov.b64 %0, {%1, %1};" : "=l"(r) : "r"(u));
    return r;
}

// ---------------------------------------------------------------------------
__global__ void init_kernel() {
    int t = blockIdx.x * blockDim.x + threadIdx.x;
    if (t < IN_CAPS * 8) { g_b[t] = 0.0f; g_C[t] = 0.125f; }
}

// b += a (both K-split partials), softmax over o -> C. Vectorized: 6 float4
// LDGs in flight (MLP 6), __expf, float4 stores.
__global__ void __launch_bounds__(128) compute_C_kernel() {
    int i = blockIdx.x * 128 + threadIdx.x;
    if (i >= IN_CAPS) return;
    const float4* b4 = reinterpret_cast<const float4*>(g_b) + i * 2;
    const float4* p4 = reinterpret_cast<const float4*>(g_bp[0]) + i * 2;
    const float4* q4 = reinterpret_cast<const float4*>(g_bp[1]) + i * 2;
    float4 b0 = b4[0], b1 = b4[1];
    float4 p0 = p4[0], p1 = p4[1];
    float4 q0 = q4[0], q1 = q4[1];
    float bv[8] = {b0.x + p0.x + q0.x, b0.y + p0.y + q0.y,
                   b0.z + p0.z + q0.z, b0.w + p0.w + q0.w,
                   b1.x + p1.x + q1.x, b1.y + p1.y + q1.y,
                   b1.z + p1.z + q1.z, b1.w + p1.w + q1.w};
    float4* bw = reinterpret_cast<float4*>(g_b) + i * 2;
    bw[0] = make_float4(bv[0], bv[1], bv[2], bv[3]);
    bw[1] = make_float4(bv[4], bv[5], bv[6], bv[7]);
    float mx = -1e30f;
#pragma unroll
    for (int o = 0; o < 8; o++) mx = fmaxf(mx, bv[o]);
    float sum = 0.0f;
#pragma unroll
    for (int o = 0; o < 8; o++) { bv[o] = __expf(bv[o] - mx); sum += bv[o]; }
    float inv = 1.0f / sum;
    float4* cw = reinterpret_cast<float4*>(g_C) + i * 2;
    cw[0] = make_float4(bv[0] * inv, bv[1] * inv, bv[2] * inv, bv[3] * inv);
    cw[1] = make_float4(bv[4] * inv, bv[5] * inv, bv[6] * inv, bv[7] * inv);
}

// ---------------------------------------------------------------------------
// S = X @ (C .* W), split-K partials. grid (2, 73) x 256 thr.
__global__ void __launch_bounds__(256, 2) gemm_S_kernel(const float* __restrict__ X,
                                                        const float* __restrict__ W) {
    __shared__ __align__(16) float Xs[8][132];
    __shared__ __align__(16) float Ms[8][132];

    int b0 = blockIdx.x * 128;
    int kstart = blockIdx.y * CHUNK;
    int kend = min(kstart + CHUNK, KTOT);
    int t = threadIdx.x;
    int tx = t & 15, ty = t >> 4;

    ull acc[8][4];
#pragma unroll
    for (int r = 0; r < 8; r++)
#pragma unroll
        for (int j = 0; j < 4; j++) acc[r][j] = 0ull;

    int xbb = t >> 1, xkp = (t & 1) * 4;
    int wl = t * 4;
    int wo = wl >> 7, wc = (wl >> 3) & 15, wd = wl & 7;
    int wcol = wo * 16 + wc;

    float4 xv = *reinterpret_cast<const float4*>(X + (size_t)(b0 + xbb) * KTOT + kstart + xkp);
    float4 wv = *reinterpret_cast<const float4*>(W + (size_t)(kstart >> 3) * 1024 + wl);
    float cc = g_C[(kstart >> 3) * 8 + wo];

    for (int k0 = kstart; k0 < kend; k0 += 8) {
        __syncthreads();
        Xs[xkp + 0][xbb] = xv.x; Xs[xkp + 1][xbb] = xv.y;
        Xs[xkp + 2][xbb] = xv.z; Xs[xkp + 3][xbb] = xv.w;
        Ms[wd + 0][wcol] = cc * wv.x; Ms[wd + 1][wcol] = cc * wv.y;
        Ms[wd + 2][wcol] = cc * wv.z; Ms[wd + 3][wcol] = cc * wv.w;
        __syncthreads();

        int kn = k0 + 8;
        if (kn < kend) {
            xv = *reinterpret_cast<const float4*>(X + (size_t)(b0 + xbb) * KTOT + kn + xkp);
            wv = *reinterpret_cast<const float4*>(W + (size_t)(kn >> 3) * 1024 + wl);
            cc = g_C[(kn >> 3) * 8 + wo];
        }

#pragma unroll
        for (int kk = 0; kk < 8; kk++) {
            ull mv[4];
#pragma unroll
            for (int jj = 0; jj < 4; jj++)
                mv[jj] = *reinterpret_cast<const ull*>(&Ms[kk][jj * 32 + tx * 2]);
            float4 xa = *reinterpret_cast<const float4*>(&Xs[kk][ty * 8]);
            float4 xb = *reinterpret_cast<const float4*>(&Xs[kk][ty * 8 + 4]);
            float xr[8] = {xa.x, xa.y, xa.z, xa.w, xb.x, xb.y, xb.z, xb.w};
#pragma unroll
            for (int rr = 0; rr < 8; rr++) {
                ull a = pack2(xr[rr]);
#pragma unroll
                for (int jj = 0; jj < 4; jj++) ffma2(acc[rr][jj], a, mv[jj]);
            }
        }
    }

    float* out = g_Spart + (size_t)blockIdx.y * (BATCH * NOC);
#pragma unroll
    for (int rr = 0; rr < 8; rr++) {
        int bb = b0 + ty * 8 + rr;
#pragma unroll
        for (int jj = 0; jj < 4; jj++)
            *reinterpret_cast<float2*>(out + (size_t)bb * NOC + jj * 32 + tx * 2) =
                *reinterpret_cast<float2*>(&acc[rr][jj]);
    }
}

// ---------------------------------------------------------------------------
// Sum 73 partials + squash. Coalesced: gg = id>>2 (contiguous columns across
// lanes), q = id&3 (partial lane). grid 128 x 256 thr.
__global__ void __launch_bounds__(256) reduce_squash_kernel(float* __restrict__ out, int last) {
    int id = blockIdx.x * 256 + threadIdx.x;
    int gg = id >> 2;
    int q = id & 3;
    const float4* sp = reinterpret_cast<const float4*>(g_Spart);

    float4 s = make_float4(0.f, 0.f, 0.f, 0.f);
#pragma unroll 8
    for (int p = q; p < NSPLIT; p += 4) {
        float4 v = sp[(size_t)p * (BATCH * NOC / 4) + gg];
        s.x += v.x; s.y += v.y; s.z += v.z; s.w += v.w;
    }
#pragma unroll
    for (int off = 1; off <= 2; off <<= 1) {
        s.x += __shfl_xor_sync(0xffffffffu, s.x, off);
        s.y += __shfl_xor_sync(0xffffffffu, s.y, off);
        s.z += __shfl_xor_sync(0xffffffffu, s.z, off);
        s.w += __shfl_xor_sync(0xffffffffu, s.w, off);
    }
    float msq = s.x * s.x + s.y * s.y + s.z * s.z + s.w * s.w;
    msq += __shfl_xor_sync(0xffffffffu, msq, 4);
    msq += __shfl_xor_sync(0xffffffffu, msq, 8);
    float f = sqrtf(msq) / (1.0f + msq);
    float4 v = make_float4(s.x * f, s.y * f, s.z * f, s.w * f);
    if (q == 0) {
        reinterpret_cast<float4*>(g_V)[gg] = v;
        if (last) reinterpret_cast<float4*>(out)[gg] = v;
    }
}

// ---------------------------------------------------------------------------
// Y = X^T @ V, K-split 2 over batch, fused agreement into g_bp[split].
// grid (301, 2) x 128 thr, occ 4 (best measured Ya config).
// CTA tile 64 K-rows x 128 cols; per-thread 8x8. ty owns capsule r0/8+ty.
__global__ void __launch_bounds__(128, 4) gemm_Ya_kernel(const float* __restrict__ X,
                                                         const float* __restrict__ W) {
    __shared__ float Xts[8][68];
    __shared__ float Vs[8][132];

    int r0 = blockIdx.x * 64;
    int split = blockIdx.y;
    int kbeg = split * 128, kfin = kbeg + 128;
    int t = threadIdx.x;
    int tx = t & 15, ty = t >> 4;

    ull acc[8][4];
#pragma unroll
    for (int r = 0; r < 8; r++)
#pragma unroll
        for (int j = 0; j < 4; j++) acc[r][j] = 0ull;

    int lkk = t >> 4;            // 0..7
    int lq = (t & 15) * 4;       // 0..60
    bool xok = (r0 + lq) < KTOT;

    float4 xv = xok ? *reinterpret_cast<const float4*>(X + (size_t)(kbeg + lkk) * KTOT + r0 + lq)
                    : make_float4(0.f, 0.f, 0.f, 0.f);
    float4 va = *reinterpret_cast<const float4*>(g_V + (kbeg + lkk) * NOC + lq);
    float4 vb = *reinterpret_cast<const float4*>(g_V + (kbeg + lkk) * NOC + lq + 64);

    for (int k0 = kbeg; k0 < kfin; k0 += 8) {
        __syncthreads();
        *reinterpret_cast<float4*>(&Xts[lkk][lq]) = xv;
        *reinterpret_cast<float4*>(&Vs[lkk][lq]) = va;
        *reinterpret_cast<float4*>(&Vs[lkk][lq + 64]) = vb;
        __syncthreads();

        int kn = k0 + 8;
        if (kn < kfin) {
            xv = xok ? *reinterpret_cast<const float4*>(X + (size_t)(kn + lkk) * KTOT + r0 + lq)
                     : make_float4(0.f, 0.f, 0.f, 0.f);
            va = *reinterpret_cast<const float4*>(g_V + (kn + lkk) * NOC + lq);
            vb = *reinterpret_cast<const float4*>(g_V + (kn + lkk) * NOC + lq + 64);
        }

#pragma unroll
        for (int kk = 0; kk < 8; kk++) {
            ull mv[4];
#pragma unroll
            for (int jj = 0; jj < 4; jj++)
                mv[jj] = *reinterpret_cast<const ull*>(&Vs[kk][jj * 32 + tx * 2]);
            float4 xa = *reinterpret_cast<const float4*>(&Xts[kk][ty * 8]);
            float4 xb = *reinterpret_cast<const float4*>(&Xts[kk][ty * 8 + 4]);
            float xr[8] = {xa.x, xa.y, xa.z, xa.w, xb.x, xb.y, xb.z, xb.w};
#pragma unroll
            for (int rr = 0; rr < 8; rr++) {
                ull a = pack2(xr[rr]);
#pragma unroll
                for (int jj = 0; jj < 4; jj++) ffma2(acc[rr][jj], a, mv[jj]);
            }
        }
    }

    // Agreement partial: a[i,o] = (1/B) sum_{c,d,k in half} W * Y
    int i = r0 / 8 + ty;
    int iw = min(i, IN_CAPS - 1);
    int ohi = tx >> 3;
    int c = (tx & 7) * 2;
    float s[4];
#pragma unroll
    for (int jj = 0; jj < 4; jj++) {
        int oo = jj * 2 + ohi;
        const float4* wp = reinterpret_cast<const float4*>(W + (size_t)iw * 1024 + oo * 128 + c * 8);
        float4 w0 = wp[0], w1 = wp[1], w2 = wp[2], w3 = wp[3];
        float wlo[8] = {w0.x, w0.y, w0.z, w0.w, w1.x, w1.y, w1.z, w1.w};
        float whi[8] = {w2.x, w2.y, w2.z, w2.w, w3.x, w3.y, w3.z, w3.w};
        float sum = 0.0f;
#pragma unroll
        for (int d = 0; d < 8; d++) {
            float2 y = *reinterpret_cast<float2*>(&acc[d][jj]);
            sum += wlo[d] * y.x + whi[d] * y.y;
        }
        s[jj] = sum;
    }
#pragma unroll
    for (int jj = 0; jj < 4; jj++) {
        s[jj] += __shfl_xor_sync(0xffffffffu, s[jj], 1);
        s[jj] += __shfl_xor_sync(0xffffffffu, s[jj], 2);
        s[jj] += __shfl_xor_sync(0xffffffffu, s[jj], 4);
    }
    if ((tx & 7) == 0 && i < IN_CAPS) {
#pragma unroll
        for (int jj = 0; jj < 4; jj++)
            g_bp[split][i * 8 + jj * 2 + ohi] = s[jj] * (1.0f / 256.0f);
    }
}

// ---------------------------------------------------------------------------
extern "C" void kernel_launch(void* const* d_in, const int* in_sizes, int n_in,
                              void* d_out, int out_size) {
    const float* x;
    const float* W;
    if (in_sizes[0] == BATCH * KTOT) {
        x = (const float*)d_in[0];
        W = (const float*)d_in[1];
    } else {
        x = (const float*)d_in[1];
        W = (const float*)d_in[0];
    }
    float* out = (float*)d_out;

    init_kernel<<<76, 256>>>();

    for (int it = 0; it < 3; it++) {
        gemm_S_kernel<<<dim3(2, NSPLIT), 256>>>(x, W);
        reduce_squash_kernel<<<128, 256>>>(out, it == 2 ? 1 : 0);
        if (it < 2) {
            gemm_Ya_kernel<<<dim3(301, 2), 128>>>(x, W);
            compute_C_kernel<<<19, 128>>>();
        }
    }
}